// round 10
// baseline (speedup 1.0000x reference)
#include <cuda_runtime.h>
#include <cuda_bf16.h>

#define NEDGE 8192
#define DD    256
#define SPLITK 16

typedef __nv_bfloat16 bf16;
typedef unsigned int u32;

// ---------------- scratch (device globals; no allocation allowed) ----------
__device__ __align__(16) bf16 g_Xh[NEDGE * DD], g_Xl[NEDGE * DD];
__device__ __align__(16) bf16 g_eh[2][NEDGE * DD], g_el[2][NEDGE * DD];
__device__ __align__(16) bf16 g_W1h[DD * DD], g_W1l[DD * DD];
__device__ __align__(16) bf16 g_W2h[DD * DD], g_W2l[DD * DD];
__device__ __align__(16) bf16 g_W3ah[DD * DD], g_W3al[DD * DD];
__device__ __align__(16) bf16 g_Ph[2][DD * DD], g_Pl[2][DD * DD];
__device__ float g_Mpart[2][SPLITK][DD * DD];

// ---------------- helpers ---------------------------------------------------
__device__ __forceinline__ void cpa16(void* dst, const void* src) {
    unsigned s = (unsigned)__cvta_generic_to_shared(dst);
    asm volatile("cp.async.cg.shared.global [%0], [%1], 16;" :: "r"(s), "l"(src));
}
__device__ __forceinline__ void cpa_commit() { asm volatile("cp.async.commit_group;"); }
__device__ __forceinline__ void cpa_wait0()  { asm volatile("cp.async.wait_group 0;"); }
__device__ __forceinline__ void cpa_wait1()  { asm volatile("cp.async.wait_group 1;"); }

__device__ __forceinline__ unsigned saddr(const void* p) {
    return (unsigned)__cvta_generic_to_shared(p);
}
__device__ __forceinline__ void ldsm_x4(u32* r, unsigned a) {
    asm volatile("ldmatrix.sync.aligned.m8n8.x4.shared.b16 {%0,%1,%2,%3}, [%4];"
        : "=r"(r[0]), "=r"(r[1]), "=r"(r[2]), "=r"(r[3]) : "r"(a));
}
__device__ __forceinline__ void ldsm_x4_t(u32* r, unsigned a) {
    asm volatile("ldmatrix.sync.aligned.m8n8.x4.trans.shared.b16 {%0,%1,%2,%3}, [%4];"
        : "=r"(r[0]), "=r"(r[1]), "=r"(r[2]), "=r"(r[3]) : "r"(a));
}
__device__ __forceinline__ void mma_bf16(float* d, const u32* a, const u32* b) {
    asm volatile(
        "mma.sync.aligned.m16n8k16.row.col.f32.bf16.bf16.f32 "
        "{%0,%1,%2,%3}, {%4,%5,%6,%7}, {%8,%9}, {%0,%1,%2,%3};"
        : "+f"(d[0]), "+f"(d[1]), "+f"(d[2]), "+f"(d[3])
        : "r"(a[0]), "r"(a[1]), "r"(a[2]), "r"(a[3]), "r"(b[0]), "r"(b[1]));
}
__device__ __forceinline__ void split_store(bf16* Hp, bf16* Lp, size_t off,
                                            float v0, float v1) {
    bf16 h0 = __float2bfloat16(v0), h1 = __float2bfloat16(v1);
    bf16 l0 = __float2bfloat16(v0 - __bfloat162float(h0));
    bf16 l1 = __float2bfloat16(v1 - __bfloat162float(h1));
    __nv_bfloat162 H; H.x = h0; H.y = h1;
    __nv_bfloat162 L; L.x = l0; L.y = l1;
    *reinterpret_cast<__nv_bfloat162*>(Hp + off) = H;
    *reinterpret_cast<__nv_bfloat162*>(Lp + off) = L;
}

// ===========================================================================
// k_cvt: float4-vectorized hi/lo conversion of X and W1/W2/W3a.
// grid 2240 x 256 (exact).
// ===========================================================================
__global__ void k_cvt(const float4* __restrict__ X4, const float4* __restrict__ W14,
                      const float4* __restrict__ W24, const float4* __restrict__ W34)
{
    const int idx = blockIdx.x * 256 + threadIdx.x;
    if (idx < 524288) {
        const float4 v = X4[idx];
        const size_t o = (size_t)idx * 4;
        split_store(g_Xh, g_Xl, o,     v.x, v.y);
        split_store(g_Xh, g_Xl, o + 2, v.z, v.w);
    } else {
        const int w = idx - 524288;
        const int which = w >> 14;
        const int off4 = w & 16383;
        const float4* S = (which == 0) ? W14 : (which == 1) ? W24 : W34;
        bf16* Hd = (which == 0) ? g_W1h : (which == 1) ? g_W2h : g_W3ah;
        bf16* Ld = (which == 0) ? g_W1l : (which == 1) ? g_W2l : g_W3al;
        const float4 v = S[off4];
        const size_t o = (size_t)off4 * 4;
        split_store(Hd, Ld, o,     v.x, v.y);
        split_store(Hd, Ld, o + 2, v.z, v.w);
    }
}

// ===========================================================================
// Core: multi-pass bf16 MMA GEMM. Block tile (MI*32) x 128, 8 warps
// (2m x 4n), warp tile (MI*16) x 32, k-tile 64, 3-stage cp.async ring.
// ===========================================================================
template <int NPASS, int MI>
__device__ __forceinline__ void mma_core_rowA(
    const bf16* const* Ap, const bf16* const* Bp,
    int rowBase, int colBase, float (&acc)[MI][4][4])
{
    extern __shared__ __align__(16) char sm_raw[];
    constexpr int AROWS = MI * 32;             // block rows
    constexpr int A_BUF = AROWS * 72;          // bf16 elems per stage
    bf16* sAs = (bf16*)sm_raw;
    bf16* sBs = (bf16*)(sm_raw + 3 * A_BUF * 2);

    auto as_e = [&](int b, int r, int c) -> bf16& { return sAs[b * A_BUF + r * 72 + c]; };
    auto bs_e = [&](int b, int r, int c) -> bf16& { return sBs[b * 8704 + r * 136 + c]; };

    const int tid = threadIdx.x;
    const int lane = tid & 31, w = tid >> 5;
    const int m0w = (w >> 2) * (MI * 16), n0w = (w & 3) * 32;

    auto prefetch = [&](int it, int bufn) {
        const int pass = it >> 2;
        const int k0 = (it & 3) * 64;
        const bf16* __restrict__ A = Ap[pass];
        const bf16* __restrict__ B = Bp[pass];
#pragma unroll
        for (int i = 0; i < MI; ++i) {         // A: AROWS x 64 k
            const int ca = tid + 256 * i;
            const int ar = ca >> 3, ao = (ca & 7) * 8;
            cpa16(&as_e(bufn, ar, ao), A + (size_t)(rowBase + ar) * DD + k0 + ao);
        }
#pragma unroll
        for (int i = 0; i < 4; ++i) {          // B: 64 k x 128 n
            const int cb = tid + 256 * i;
            const int br = cb >> 4, bo = (cb & 15) * 8;
            cpa16(&bs_e(bufn, br, bo), B + (size_t)(k0 + br) * DD + colBase + bo);
        }
        cpa_commit();
    };

    const int t = lane >> 3;
    const int aro = (t & 1) * 8 + (lane & 7);
    const int aco = (t >> 1) * 8;
    const int bro2 = (lane & 7) + ((lane >> 3) & 1) * 8;
    const int bco2 = (lane >> 4) * 8;

    constexpr int NIT = NPASS * 4;
    prefetch(0, 0);
    prefetch(1, 1);
    for (int it = 0; it < NIT; ++it) {
        cpa_wait1();
        __syncthreads();
        if (it + 2 < NIT) prefetch(it + 2, (it + 2) % 3);
        else cpa_commit();   // keep wait-group arithmetic exact
        const int buf = it % 3;
#pragma unroll
        for (int ki = 0; ki < 4; ++ki) {
            u32 a[MI][4], bq[2][4];
#pragma unroll
            for (int mi = 0; mi < MI; ++mi)
                ldsm_x4(a[mi], saddr(&as_e(buf, m0w + mi * 16 + aro, ki * 16 + aco)));
#pragma unroll
            for (int nj = 0; nj < 2; ++nj)
                ldsm_x4_t(bq[nj], saddr(&bs_e(buf, ki * 16 + bro2, n0w + nj * 16 + bco2)));
#pragma unroll
            for (int mi = 0; mi < MI; ++mi)
#pragma unroll
                for (int ni = 0; ni < 4; ++ni)
                    mma_bf16(acc[mi][ni], a[mi], &bq[ni >> 1][(ni & 1) * 2]);
        }
    }
}

// ===========================================================================
// k_e_mma: e_z = relu(X @ W_z + b_z) -> bf16 hi/lo. grid (2, 64, 2) x 256.
// ===========================================================================
__global__ void __launch_bounds__(256, 2)
k_e_mma(const float* __restrict__ b1, const float* __restrict__ b2)
{
    const int z = blockIdx.z;
    const bf16* Ap[3] = {g_Xh, g_Xh, g_Xl};
    const bf16* Bp[3] = {z ? g_W2h : g_W1h, z ? g_W2l : g_W1l, z ? g_W2h : g_W1h};
    const float* __restrict__ bias = z ? b2 : b1;
    bf16* __restrict__ Eh = g_eh[z];
    bf16* __restrict__ El = g_el[z];

    const int rowBase = blockIdx.y * 128, colBase = blockIdx.x * 128;
    float acc[4][4][4] = {};
    mma_core_rowA<3, 4>(Ap, Bp, rowBase, colBase, acc);

    const int lane = threadIdx.x & 31, w = threadIdx.x >> 5;
    const int m0w = (w >> 2) * 64, n0w = (w & 3) * 32;
    const int r_l = lane >> 2, c_l = (lane & 3) * 2;
#pragma unroll
    for (int mi = 0; mi < 4; ++mi)
#pragma unroll
        for (int ni = 0; ni < 4; ++ni) {
            const int col = colBase + n0w + ni * 8 + c_l;
            const float2 bb = *(const float2*)&bias[col];
#pragma unroll
            for (int h = 0; h < 2; ++h) {
                const int r = rowBase + m0w + mi * 16 + r_l + h * 8;
                float v0 = fmaxf(acc[mi][ni][h * 2 + 0] + bb.x, 0.f);
                float v1 = fmaxf(acc[mi][ni][h * 2 + 1] + bb.y, 0.f);
                split_store(Eh, El, (size_t)r * DD + col, v0, v1);
            }
        }
}

// ===========================================================================
// k_mpart_mma: split-K partials of M_z = e_zᵀ @ X (trans-A ldmatrix).
// grid (2, 2, 32) x 256, k-tile 64, 3-stage ring.
// ===========================================================================
#define ES_ELEM(b, r, c) sEs[(b) * 8704 + (r) * 136 + (c)]
#define XS_ELEM(b, r, c) sXs[(b) * 8704 + (r) * 136 + (c)]

__global__ void __launch_bounds__(256, 2)
k_mpart_mma()
{
    const int mat = blockIdx.z >> 4, split = blockIdx.z & 15;
    const bf16* Ap[3] = {g_eh[mat], g_eh[mat], g_el[mat]};
    const bf16* Bp[3] = {g_Xh, g_Xl, g_Xh};
    float* __restrict__ Cp = g_Mpart[mat][split];

    extern __shared__ __align__(16) char sm_raw[];
    bf16* sEs = (bf16*)sm_raw;
    bf16* sXs = (bf16*)(sm_raw + 52224);

    const int tid = threadIdx.x;
    const int lane = tid & 31, w = tid >> 5;
    const int m0w = (w >> 2) * 64, n0w = (w & 3) * 32;
    const int mBase = blockIdx.y * 128, nBase = blockIdx.x * 128;
    const int i0 = split * (NEDGE / SPLITK);

    auto prefetch = [&](int it, int bufn) {
        const int pass = it >> 3;
        const int e0 = i0 + (it & 7) * 64;
        const bf16* __restrict__ E = Ap[pass];
        const bf16* __restrict__ X = Bp[pass];
#pragma unroll
        for (int i = 0; i < 4; ++i) {
            const int c = tid + 256 * i;                // 64 rows x 128 cols
            const int r = c >> 4, o = (c & 15) * 8;
            cpa16(&ES_ELEM(bufn, r, o), E + (size_t)(e0 + r) * DD + mBase + o);
            cpa16(&XS_ELEM(bufn, r, o), X + (size_t)(e0 + r) * DD + nBase + o);
        }
        cpa_commit();
    };

    const int t = lane >> 3;
    const int akro = (t >> 1) * 8 + (lane & 7);
    const int amco = (t & 1) * 8;
    const int bro2 = (lane & 7) + ((lane >> 3) & 1) * 8;
    const int bco2 = (lane >> 4) * 8;

    float acc[4][4][4] = {};
    prefetch(0, 0);
    prefetch(1, 1);
    for (int it = 0; it < 24; ++it) {
        cpa_wait1();
        __syncthreads();
        if (it + 2 < 24) prefetch(it + 2, (it + 2) % 3);
        else cpa_commit();
        const int buf = it % 3;
#pragma unroll
        for (int ki = 0; ki < 4; ++ki) {
            u32 a[4][4], bq[2][4];
#pragma unroll
            for (int mi = 0; mi < 4; ++mi)
                ldsm_x4_t(a[mi], saddr(&ES_ELEM(buf, ki * 16 + akro, m0w + mi * 16 + amco)));
#pragma unroll
            for (int nj = 0; nj < 2; ++nj)
                ldsm_x4_t(bq[nj], saddr(&XS_ELEM(buf, ki * 16 + bro2, n0w + nj * 16 + bco2)));
#pragma unroll
            for (int mi = 0; mi < 4; ++mi)
#pragma unroll
                for (int ni = 0; ni < 4; ++ni)
                    mma_bf16(acc[mi][ni], a[mi], &bq[ni >> 1][(ni & 1) * 2]);
        }
    }

    const int r_l = lane >> 2, c_l = (lane & 3) * 2;
#pragma unroll
    for (int mi = 0; mi < 4; ++mi)
#pragma unroll
        for (int ni = 0; ni < 4; ++ni) {
            const int col = nBase + n0w + ni * 8 + c_l;
#pragma unroll
            for (int h = 0; h < 2; ++h) {
                const int r = mBase + m0w + mi * 16 + r_l + h * 8;
                float2 v = make_float2(acc[mi][ni][h * 2 + 0], acc[mi][ni][h * 2 + 1]);
                *(float2*)&Cp[(size_t)r * DD + col] = v;
            }
        }
}

// ===========================================================================
// k_p (FUSED reduce + GEMM + convert): P_z = (sum_p Mpart_z,p / D) @ W3b_z,
// emitted as bf16 hi/lo. Out tile 8 x 128, K chunks of 64: B streams via
// cp.async while threads 0..127 reduce the A chunk from L2. grid (2,32,2).
// ===========================================================================
__global__ void __launch_bounds__(256)
k_p(const float* __restrict__ W3)
{
    const int mat = blockIdx.z;
    const int mBase = blockIdx.y * 8, nBase = blockIdx.x * 128;
    const float* __restrict__ B = W3 + (size_t)(DD + mat * DD) * DD;

    __shared__ float sA[8][68];
    __shared__ __align__(16) float Bs[64][132];

    const int tid = threadIdx.x;
    const int ty = tid >> 5, tx = tid & 31;
    float acc[4] = {};

    for (int kt = 0; kt < DD; kt += 64) {
        // B chunk: 64 x 128 f32 = 2048 float4, 8 per thread
#pragma unroll
        for (int i = 0; i < 8; ++i) {
            const int cb = tid + 256 * i;
            const int r = cb >> 5, c = (cb & 31) * 4;
            cpa16(&Bs[r][c], &B[(size_t)(kt + r) * DD + nBase + c]);
        }
        cpa_commit();
        // A chunk reduce: 8 rows x 64 cols = 128 float4, threads 0..127
        if (tid < 128) {
            const int r = tid >> 4, c = (tid & 15) * 4;
            const size_t ai = (size_t)(mBase + r) * DD + kt + c;
            float4 s = *(const float4*)&g_Mpart[mat][0][ai];
#pragma unroll
            for (int p = 1; p < SPLITK; ++p) {
                const float4 v = *(const float4*)&g_Mpart[mat][p][ai];
                s.x += v.x; s.y += v.y; s.z += v.z; s.w += v.w;
            }
            const float sc = 1.0f / DD;
            sA[r][c + 0] = s.x * sc; sA[r][c + 1] = s.y * sc;
            sA[r][c + 2] = s.z * sc; sA[r][c + 3] = s.w * sc;
        }
        cpa_wait0();
        __syncthreads();
#pragma unroll
        for (int kk = 0; kk < 64; ++kk) {
            const float a = sA[ty][kk];
            const float4 b4 = *(const float4*)&Bs[kk][tx * 4];
            acc[0] = fmaf(a, b4.x, acc[0]);
            acc[1] = fmaf(a, b4.y, acc[1]);
            acc[2] = fmaf(a, b4.z, acc[2]);
            acc[3] = fmaf(a, b4.w, acc[3]);
        }
        __syncthreads();
    }

    const size_t o = (size_t)(mBase + ty) * DD + nBase + tx * 4;
    split_store(g_Ph[mat], g_Pl[mat], o,     acc[0], acc[1]);
    split_store(g_Ph[mat], g_Pl[mat], o + 2, acc[2], acc[3]);
}

// ===========================================================================
// k_final_mma: out = relu(X@W3a + e1@P1 + e2@P2 + b3). 7 passes, 64-row
// tiles (MI=2) -> grid (2, 128) = 256 blocks for real 2-CTA/SM overlap.
// ===========================================================================
__global__ void __launch_bounds__(256, 2)
k_final_mma(const float* __restrict__ b3, float* __restrict__ out)
{
    const bf16* Ap[7] = {g_Xh,
                         g_eh[0], g_eh[0], g_el[0],
                         g_eh[1], g_eh[1], g_el[1]};
    const bf16* Bp[7] = {g_W3ah,
                         g_Ph[0], g_Pl[0], g_Ph[0],
                         g_Ph[1], g_Pl[1], g_Ph[1]};

    const int rowBase = blockIdx.y * 64, colBase = blockIdx.x * 128;
    float acc[2][4][4] = {};
    mma_core_rowA<7, 2>(Ap, Bp, rowBase, colBase, acc);

    const int lane = threadIdx.x & 31, w = threadIdx.x >> 5;
    const int m0w = (w >> 2) * 32, n0w = (w & 3) * 32;
    const int r_l = lane >> 2, c_l = (lane & 3) * 2;
#pragma unroll
    for (int mi = 0; mi < 2; ++mi)
#pragma unroll
        for (int ni = 0; ni < 4; ++ni) {
            const int col = colBase + n0w + ni * 8 + c_l;
            const float2 bb = *(const float2*)&b3[col];
#pragma unroll
            for (int h = 0; h < 2; ++h) {
                const int r = rowBase + m0w + mi * 16 + r_l + h * 8;
                float2 v;
                v.x = fmaxf(acc[mi][ni][h * 2 + 0] + bb.x, 0.f);
                v.y = fmaxf(acc[mi][ni][h * 2 + 1] + bb.y, 0.f);
                *(float2*)&out[(size_t)r * DD + col] = v;
            }
        }
}

// ---------------------------------------------------------------------------
// Inputs (metadata order):
// 0 edge_pred[8192] f32 | 1 edge_corner[8192,2] i64 | 2 all_corners[4096,2] f32
// 3 edge_x[8192,256] f32 | 4 image_x[1024] f32 | 5 W1[256,256] | 6 b1[256]
// 7 W2[256,256] | 8 b2[256] | 9 W3[768,256] | 10 b3[256]
// Output: [8192, 256] f32
// ---------------------------------------------------------------------------
extern "C" void kernel_launch(void* const* d_in, const int* in_sizes, int n_in,
                              void* d_out, int out_size)
{
    (void)in_sizes; (void)n_in; (void)out_size;
    const float* X  = (const float*)d_in[3];
    const float* W1 = (const float*)d_in[5];
    const float* b1 = (const float*)d_in[6];
    const float* W2 = (const float*)d_in[7];
    const float* b2 = (const float*)d_in[8];
    const float* W3 = (const float*)d_in[9];
    const float* b3 = (const float*)d_in[10];
    float* out = (float*)d_out;

    const int SMEM_E     = 3 * 128 * 72 * 2 + 3 * 64 * 136 * 2;  // 107520 B
    const int SMEM_FINAL = 3 * 64 * 72 * 2 + 3 * 64 * 136 * 2;   //  79872 B
    const int SMEM_MPART = 2 * 52224;                             // 104448 B
    cudaFuncSetAttribute(k_e_mma, cudaFuncAttributeMaxDynamicSharedMemorySize, SMEM_E);
    cudaFuncSetAttribute(k_final_mma, cudaFuncAttributeMaxDynamicSharedMemorySize, SMEM_FINAL);
    cudaFuncSetAttribute(k_mpart_mma, cudaFuncAttributeMaxDynamicSharedMemorySize, SMEM_MPART);

    k_cvt<<<2240, 256>>>((const float4*)X, (const float4*)W1,
                         (const float4*)W2, (const float4*)W3);
    k_e_mma<<<dim3(2, 64, 2), 256, SMEM_E>>>(b1, b2);
    k_mpart_mma<<<dim3(2, 2, 32), 256, SMEM_MPART>>>();
    k_p<<<dim3(2, 32, 2), 256>>>(W3);
    k_final_mma<<<dim3(2, 128), 256, SMEM_FINAL>>>(b3, out);
}